// round 9
// baseline (speedup 1.0000x reference)
#include <cuda_runtime.h>

#define H_IMG 512
#define W_IMG 512
#define NPLANES 96            // 32 * 3
#define TW 32
#define TH 32
#define IW 42                 // TW + 10
#define IH 42                 // TH + 10
#define SS 43                 // staged-input smem row stride (odd -> conflict-free)
#define MS 33                 // intermediate smem row stride (conflict-free)
#define NT 256
#define NBX 16                // 512/32
#define NBY 16                // 512/32
#define NBLK (NBX * NBY * NPLANES)   // 24576
#define C1F 6.5025f
#define C2F 58.5225f
#define NPIX 25165824.0       // 32*3*512*512

__device__ float g_partials[NBLK];
__device__ unsigned int g_count = 0;

#define W11_INIT {0.00102838f, 0.00759871f, 0.03600077f, 0.10936070f, \
                  0.21300560f, 0.26601180f, 0.21300560f, 0.10936070f, \
                  0.03600077f, 0.00759871f, 0.00102838f}

__global__ void __launch_bounds__(NT, 6) ssim_main(const float* __restrict__ gen,
                                                   const float* __restrict__ ref,
                                                   float* __restrict__ out) {
    __shared__ float sg[IH * SS];      // staged gen (scaled)
    __shared__ float sr[IH * SS];      // staged ref (scaled)
    __shared__ float m1[IH * MS];      // conv_h(g)
    __shared__ float m2[IH * MS];      // conv_h(r)
    __shared__ float mss[IH * MS];     // conv_h(g^2 + r^2)
    __shared__ float mgr[IH * MS];     // conv_h(g*r)
    __shared__ float wsum[8];
    __shared__ double dsum[8];
    __shared__ bool is_last;

    const float W11[11] = W11_INIT;    // compile-time consts -> FFMA-imm

    const int tid = threadIdx.x;
    const int lane = tid & 31;
    const int wrp = tid >> 5;
    const int x0 = blockIdx.x * TW;
    const int y0 = blockIdx.y * TH;
    const size_t pb = (size_t)blockIdx.z * (size_t)(H_IMG * W_IMG);
    const float* gp = gen + pb;
    const float* rp = ref + pb;

    // ---- Stage 0: warp-per-row coalesced load, scale, zero-pad ----
    const bool interior = (x0 >= 5) & (x0 + IW - 5 <= W_IMG) &
                          (y0 >= 5) & (y0 + IH - 5 <= H_IMG);
    if (interior) {
        const float* gb = gp + (long)(y0 - 5) * W_IMG + (x0 - 5);
        const float* rb = rp + (long)(y0 - 5) * W_IMG + (x0 - 5);
#pragma unroll
        for (int r = wrp; r < IH; r += 8) {
            const float* grow = gb + (long)r * W_IMG;
            const float* rrow = rb + (long)r * W_IMG;
            float* sgrow = sg + r * SS;
            float* srrow = sr + r * SS;
            sgrow[lane] = fmaf(grow[lane], 0.5f, 0.5f);
            srrow[lane] = fmaf(rrow[lane], 0.5f, 0.5f);
            if (lane < IW - 32) {
                sgrow[lane + 32] = fmaf(grow[lane + 32], 0.5f, 0.5f);
                srrow[lane + 32] = fmaf(rrow[lane + 32], 0.5f, 0.5f);
            }
        }
    } else {
#pragma unroll
        for (int r = wrp; r < IH; r += 8) {
            int gy = y0 + r - 5;
            bool rowok = (unsigned)gy < (unsigned)H_IMG;
            const float* grow = gp + (long)gy * W_IMG;
            const float* rrow = rp + (long)gy * W_IMG;
            float* sgrow = sg + r * SS;
            float* srrow = sr + r * SS;
#pragma unroll
            for (int h = 0; h < 2; h++) {
                int c = lane + h * 32;
                if (c < IW) {
                    int gx = x0 + c - 5;
                    bool ok = rowok && ((unsigned)gx < (unsigned)W_IMG);
                    sgrow[c] = ok ? fmaf(grow[gx], 0.5f, 0.5f) : 0.f;
                    srrow[c] = ok ? fmaf(rrow[gx], 0.5f, 0.5f) : 0.f;
                }
            }
        }
    }
    __syncthreads();

    // ---- Stage 1: horizontal conv, 4 fields SEQUENTIALLY (low reg pressure),
    //      4 output cols per item; items: 42 rows x 8 chunks = 336 ----
#define HCONV_STORE(SRC, DST)                                             \
        {                                                                 \
            float s[4] = {0.f, 0.f, 0.f, 0.f};                            \
            _Pragma("unroll")                                             \
            for (int k = 0; k < 11; k++) {                                \
                _Pragma("unroll")                                         \
                for (int j = 0; j < 4; j++)                               \
                    s[j] = fmaf(W11[k], SRC[k + j], s[j]);                \
            }                                                             \
            _Pragma("unroll")                                             \
            for (int j = 0; j < 4; j++) DST[o + j] = s[j];                \
        }

#pragma unroll
    for (int pass = 0; pass < 2; pass++) {
        int item = tid + pass * NT;
        if (item < IH * 8) {
            int r = item >> 3;
            int c0 = (item & 7) << 2;
            const float* sgr = sg + r * SS + c0;
            const float* srr = sr + r * SS + c0;
            const int o = r * MS + c0;

            float a[14], b[14];
#pragma unroll
            for (int t = 0; t < 14; t++) { a[t] = sgr[t]; b[t] = srr[t]; }

            HCONV_STORE(a, m1)
            HCONV_STORE(b, m2)

            // in-place transform: a <- g^2 + r^2,  b <- g*r
#pragma unroll
            for (int t = 0; t < 14; t++) {
                float pa = a[t];
                float pbv = b[t];
                a[t] = fmaf(pa, pa, pbv * pbv);
                b[t] = pa * pbv;
            }

            HCONV_STORE(a, mss)
            HCONV_STORE(b, mgr)
        }
    }
#undef HCONV_STORE
    __syncthreads();

    // ---- Stage 2: vertical conv (4 rows/thread), streaming SSIM combine ----
    float lsum = 0.f;
    {
        const int c = lane;
        const int r0 = wrp << 2;       // 8 warps * 4 rows = 32

#define VCONV(MARR, OUT)                                                  \
        {                                                                 \
            float v[14];                                                  \
            _Pragma("unroll")                                             \
            for (int t = 0; t < 14; t++) v[t] = MARR[(r0 + t) * MS + c];  \
            _Pragma("unroll")                                             \
            for (int j = 0; j < 4; j++) {                                 \
                float acc = 0.f;                                          \
                _Pragma("unroll")                                         \
                for (int k = 0; k < 11; k++)                              \
                    acc = fmaf(W11[k], v[j + k], acc);                    \
                OUT[j] = acc;                                             \
            }                                                             \
        }

        float q[4], p[4];              // mu1^2+mu2^2, mu1*mu2
        {
            float o1[4], o2[4];
            VCONV(m1, o1)
            VCONV(m2, o2)
#pragma unroll
            for (int j = 0; j < 4; j++) {
                q[j] = fmaf(o1[j], o1[j], o2[j] * o2[j]);
                p[j] = o1[j] * o2[j];
            }
        }
        float dden[4];
        {
            float oss[4];
            VCONV(mss, oss)
#pragma unroll
            for (int j = 0; j < 4; j++)
                dden[j] = (q[j] + C1F) * (oss[j] - q[j] + C2F);
        }
        {
            float ogr[4];
            VCONV(mgr, ogr)
#pragma unroll
            for (int j = 0; j < 4; j++) {
                float num = fmaf(2.f, p[j], C1F) * fmaf(2.f, ogr[j] - p[j], C2F);
                lsum += __fdividef(num, dden[j]);
            }
        }
#undef VCONV
    }

    // ---- Block reduction (fp32) ----
#pragma unroll
    for (int off = 16; off > 0; off >>= 1)
        lsum += __shfl_xor_sync(0xffffffffu, lsum, off);
    if (lane == 0) wsum[wrp] = lsum;
    __syncthreads();

    if (tid == 0) {
        float s = 0.f;
#pragma unroll
        for (int i = 0; i < 8; i++) s += wsum[i];
        int bid = blockIdx.x + NBX * (blockIdx.y + NBY * blockIdx.z);
        g_partials[bid] = s;
        __threadfence();
        unsigned int t = atomicAdd(&g_count, 1u);
        is_last = (t == (unsigned)(NBLK - 1));
    }
    __syncthreads();

    // ---- Last block: deterministic final reduction ----
    if (is_last) {
        __threadfence();
        double acc = 0.0;
        for (int i = tid; i < NBLK; i += NT)
            acc += (double)g_partials[i];
#pragma unroll
        for (int off = 16; off > 0; off >>= 1)
            acc += __shfl_xor_sync(0xffffffffu, acc, off);
        if (lane == 0) dsum[wrp] = acc;
        __syncthreads();
        if (tid == 0) {
            double s = 0.0;
#pragma unroll
            for (int i = 0; i < 8; i++) s += dsum[i];
            out[0] = (float)(1.0 - s / NPIX);
            g_count = 0;   // self-reset -> graph-replay deterministic
        }
    }
}

extern "C" void kernel_launch(void* const* d_in, const int* in_sizes, int n_in,
                              void* d_out, int out_size) {
    const float* gen = (const float*)d_in[0];
    const float* ref = (const float*)d_in[1];
    float* out = (float*)d_out;

    dim3 grid(NBX, NBY, NPLANES);
    ssim_main<<<grid, NT>>>(gen, ref, out);
}